// round 2
// baseline (speedup 1.0000x reference)
#include <cuda_runtime.h>
#include <cuda_bf16.h>

// Router: logits = x@W + b  (N=16384, D=2048, E=64), softmax, top-2, aux loss.
// Output layout (float32): [weights N*2][indices-as-float N*2][aux 1]

#define DDIM 2048
#define EDIM 64
#define BM 64
#define BK 32
#define APAD 68   // row stride for transposed A tile: 68*4 bytes divisible by 16

__device__ float g_cnt[EDIM];
__device__ float g_prob[EDIM];

__global__ void zero_acc_kernel() {
    int t = threadIdx.x;
    if (t < EDIM) { g_cnt[t] = 0.0f; g_prob[t] = 0.0f; }
}

__global__ __launch_bounds__(256, 2)
void router_main_kernel(const float* __restrict__ x,
                        const float* __restrict__ W,
                        const float* __restrict__ b,
                        float* __restrict__ out, int N)
{
    __shared__ float As[BK][APAD];        // transposed A tile: As[k][m]
    __shared__ float Bs[BK][EDIM];        // Bs[k][e]
    __shared__ float lg[BM][EDIM + 1];    // logits tile (padded)
    __shared__ float rmax[BM];
    __shared__ float rinv[BM];
    __shared__ int   cnt_s[EDIM];

    const int tid = threadIdx.x;
    const int tx = tid & 15;              // expert quad
    const int ty = tid >> 4;              // token quad
    const int row0 = blockIdx.x * BM;

    // bias for this thread's 4 experts (hoisted out of the loop)
    float bj[4];
    #pragma unroll
    for (int j = 0; j < 4; j++) bj[j] = b[(tx << 2) + j];

    float acc[4][4];
    #pragma unroll
    for (int i = 0; i < 4; i++)
        #pragma unroll
        for (int j = 0; j < 4; j++) acc[i][j] = 0.0f;

    for (int k0 = 0; k0 < DDIM; k0 += BK) {
        // ---- load A tile (64 tokens x 32 k), store transposed ----
        #pragma unroll
        for (int l = 0; l < 2; l++) {
            int i = tid + l * 256;        // 0..511
            int m  = i >> 3;              // token within tile
            int kq = (i & 7) << 2;        // k offset (float4 granularity)
            float4 v = *(const float4*)(x + (size_t)(row0 + m) * DDIM + k0 + kq);
            As[kq + 0][m] = v.x;
            As[kq + 1][m] = v.y;
            As[kq + 2][m] = v.z;
            As[kq + 3][m] = v.w;
        }
        // ---- load B tile (32 k x 64 experts) ----
        #pragma unroll
        for (int l = 0; l < 2; l++) {
            int i = tid + l * 256;        // 0..511
            int k = i >> 4;
            int q = (i & 15) << 2;
            *(float4*)(&Bs[k][q]) = *(const float4*)(W + (size_t)(k0 + k) * EDIM + q);
        }
        __syncthreads();

        #pragma unroll
        for (int k = 0; k < BK; k++) {
            float4 a  = *(const float4*)(&As[k][ty << 2]);
            float4 bb = *(const float4*)(&Bs[k][tx << 2]);
            float av[4] = {a.x, a.y, a.z, a.w};
            float bv[4] = {bb.x, bb.y, bb.z, bb.w};
            #pragma unroll
            for (int i = 0; i < 4; i++)
                #pragma unroll
                for (int j = 0; j < 4; j++)
                    acc[i][j] += av[i] * bv[j];
        }
        __syncthreads();
    }

    // ---- bias + spill logits tile to smem ----
    #pragma unroll
    for (int i = 0; i < 4; i++)
        #pragma unroll
        for (int j = 0; j < 4; j++)
            lg[(ty << 2) + i][(tx << 2) + j] = acc[i][j] + bj[j];

    if (tid < EDIM) cnt_s[tid] = 0;
    __syncthreads();

    // ---- per-token pass: top-2 + softmax normalizer + outputs ----
    // 2 threads per token: thread h scans experts [h*32, h*32+32).
    if (tid < 2 * BM) {
        const int m = tid >> 1;
        const int h = tid & 1;
        const int e0 = h << 5;
        float v1 = -3.0e38f, v2 = -3.0e38f;
        int i1 = 0, i2 = 0;
        float s = 0.0f;
        #pragma unroll 8
        for (int e = e0; e < e0 + 32; e++) {
            float l = lg[m][e];
            if (l > v1)      { v2 = v1; i2 = i1; v1 = l; i1 = e; }
            else if (l > v2) { v2 = l; i2 = e; }
        }
        // merge partner halves (partner is tid^1, same warp since 2*m,2*m+1 adjacent)
        unsigned mask = __activemask();
        float pv1 = __shfl_xor_sync(0xffffffffu, v1, 1);
        float pv2 = __shfl_xor_sync(0xffffffffu, v2, 1);
        int   pi1 = __shfl_xor_sync(0xffffffffu, i1, 1);
        int   pi2 = __shfl_xor_sync(0xffffffffu, i2, 1);
        (void)mask;
        // combine (v1,i1,v2,i2) with (pv1,pi1,pv2,pi2)
        if (pv1 > v1) {
            if (v1 > pv2) { v2 = v1; i2 = i1; }
            else          { v2 = pv2; i2 = pi2; }
            v1 = pv1; i1 = pi1;
        } else {
            if (pv1 > v2) { v2 = pv1; i2 = pi1; }
        }
        // softmax partial sum over this half, with global max v1
        #pragma unroll 8
        for (int e = e0; e < e0 + 32; e++) s += __expf(lg[m][e] - v1);
        s += __shfl_xor_sync(0xffffffffu, s, 1);

        if (h == 0) {
            float inv = 1.0f / s;
            rmax[m] = v1;
            rinv[m] = inv;

            int g = row0 + m;
            out[2 * g + 0] = inv;                       // exp(v1-v1)/s
            out[2 * g + 1] = __expf(v2 - v1) * inv;
            float* oi = out + 2 * (size_t)N;
            oi[2 * g + 0] = (float)i1;
            oi[2 * g + 1] = (float)i2;

            atomicAdd(&cnt_s[i1], 1);
            atomicAdd(&cnt_s[i2], 1);
        }
    }
    __syncthreads();

    // ---- per-expert pass: prob sums + global accumulation ----
    if (tid < EDIM) {
        const int e = tid;
        float s = 0.0f;
        #pragma unroll 8
        for (int m = 0; m < BM; m++)
            s += __expf(lg[m][e] - rmax[m]) * rinv[m];
        atomicAdd(&g_prob[e], s);
        atomicAdd(&g_cnt[e], (float)cnt_s[e]);
    }
}

__global__ void finalize_kernel(float* __restrict__ out, int N) {
    __shared__ float red[64];
    int t = threadIdx.x;
    float invN = 1.0f / (float)N;
    float v = (g_cnt[t] * invN) * (g_prob[t] * invN);
    red[t] = v;
    __syncthreads();
    if (t < 32) {
        float s = red[t] + red[t + 32];
        #pragma unroll
        for (int o = 16; o > 0; o >>= 1)
            s += __shfl_down_sync(0xffffffffu, s, o);
        if (t == 0) out[4 * (size_t)N] = (float)EDIM * s;
    }
}

extern "C" void kernel_launch(void* const* d_in, const int* in_sizes, int n_in,
                              void* d_out, int out_size) {
    const float* x = (const float*)d_in[0];
    const float* W = (const float*)d_in[1];
    const float* b = (const float*)d_in[2];
    // d_in[3] is k (==2), hardcoded in the kernel.
    int N = in_sizes[0] / DDIM;   // 16384

    float* out = (float*)d_out;
    zero_acc_kernel<<<1, 64>>>();
    router_main_kernel<<<N / BM, 256>>>(x, W, b, out, N);
    finalize_kernel<<<1, 64>>>(out, N);
}

// round 8
// speedup vs baseline: 1.4709x; 1.4709x over previous
#include <cuda_runtime.h>
#include <cstdint>

// Router: logits = x@W + b (N=16384, D=2048, E=64), softmax, top-2, aux loss.
// tf32 mma 3-pass (rna hi/lo split), split accumulators + per-chunk drain to
// FFMA fp32 sums to defeat tensor-core truncating C-add bias.
// Output layout (float32): [weights N*2][indices-as-float N*2][aux 1]

#define DDIM   2048
#define EDIM   64
#define BM     128
#define BK     32
#define NCHUNK (DDIM / BK)      // 64

#define ASTRIDE 36
#define BSTRIDE 72

// float-indexed static smem layout
#define A_OFF     0                          // 128 x 36 = 4608
#define B_OFF     4608                       // 32 x 72  = 2304 -> 6912
#define LG_OFF    0                          // reuse: 128 x 65 = 8320
#define LG_STRIDE 65
#define BIAS_OFF  8320                       // 64 floats
#define CNT_OFF   8384                       // 64 ints
#define SMEM_FLOATS 8448                     // 33792 bytes

__device__ float g_cnt[EDIM];
__device__ float g_prob[EDIM];

__global__ void zero_acc_kernel() {
    int t = threadIdx.x;
    if (t < EDIM) { g_cnt[t] = 0.0f; g_prob[t] = 0.0f; }
}

__device__ __forceinline__ void mma8(float d[4],
                                     uint32_t a0, uint32_t a1, uint32_t a2, uint32_t a3,
                                     uint32_t b0, uint32_t b1) {
    asm volatile(
        "mma.sync.aligned.m16n8k8.row.col.f32.tf32.tf32.f32 "
        "{%0,%1,%2,%3}, {%4,%5,%6,%7}, {%8,%9}, {%0,%1,%2,%3};"
        : "+f"(d[0]), "+f"(d[1]), "+f"(d[2]), "+f"(d[3])
        : "r"(a0), "r"(a1), "r"(a2), "r"(a3), "r"(b0), "r"(b1));
}

__device__ __forceinline__ uint32_t tf32rna(float v) {
    uint32_t r;
    asm("cvt.rna.tf32.f32 %0, %1;" : "=r"(r) : "f"(v));
    return r;
}
__device__ __forceinline__ void split2(float v, uint32_t& hi, uint32_t& lo) {
    hi = tf32rna(v);
    lo = tf32rna(v - __uint_as_float(hi));
}

__global__ void __launch_bounds__(256)
router_main_kernel(const float* __restrict__ x,
                   const float* __restrict__ W,
                   const float* __restrict__ b,
                   float* __restrict__ out, int N)
{
    __shared__ float sm[SMEM_FLOATS];
    const int tid  = threadIdx.x;
    const int lane = tid & 31;
    const int wid  = tid >> 5;
    const int wr   = wid >> 1;      // warp row: tokens [32*wr, +32)
    const int wc   = wid & 1;       // warp col: experts [32*wc, +32)
    const int g    = lane >> 2;
    const int tg   = lane & 3;
    const int row0 = blockIdx.x * BM;

    float sum[2][4][4];     // FFMA-maintained main sums (unbiased)
    float acc[2][4][4];     // TC hh accumulator, drained each chunk
    float cor[2][4][4];     // TC correction accumulator (small magnitude)
    #pragma unroll
    for (int mf = 0; mf < 2; mf++)
        #pragma unroll
        for (int nf = 0; nf < 4; nf++)
            #pragma unroll
            for (int i = 0; i < 4; i++) {
                sum[mf][nf][i] = 0.0f; acc[mf][nf][i] = 0.0f; cor[mf][nf][i] = 0.0f;
            }

    // ---- prefetch chunk 0 into registers ----
    float4 a4[4]; float bw[8];
    {
        const float* xp = x + (size_t)row0 * DDIM;
        #pragma unroll
        for (int j = 0; j < 4; j++) {
            int idx = tid + j * 256;
            a4[j] = *(const float4*)(xp + (size_t)(idx >> 3) * DDIM + ((idx & 7) << 2));
        }
        #pragma unroll
        for (int j = 0; j < 8; j++) {
            int idx = tid + j * 256;
            bw[j] = W[(size_t)(idx >> 6) * EDIM + (idx & 63)];
        }
    }

    for (int c = 0; c < NCHUNK; c++) {
        // ---- store current chunk regs -> smem ----
        #pragma unroll
        for (int j = 0; j < 4; j++) {
            int idx = tid + j * 256;
            *(float4*)(sm + A_OFF + (idx >> 3) * ASTRIDE + ((idx & 7) << 2)) = a4[j];
        }
        #pragma unroll
        for (int j = 0; j < 8; j++) {
            int idx = tid + j * 256;
            sm[B_OFF + (idx >> 6) * BSTRIDE + (idx & 63)] = bw[j];
        }
        __syncthreads();

        // ---- issue global loads for chunk c+1 (overlap with MMAs) ----
        if (c + 1 < NCHUNK) {
            const int k0 = (c + 1) * BK;
            const float* xp = x + (size_t)row0 * DDIM + k0;
            #pragma unroll
            for (int j = 0; j < 4; j++) {
                int idx = tid + j * 256;
                a4[j] = *(const float4*)(xp + (size_t)(idx >> 3) * DDIM + ((idx & 7) << 2));
            }
            #pragma unroll
            for (int j = 0; j < 8; j++) {
                int idx = tid + j * 256;
                bw[j] = W[(size_t)(k0 + (idx >> 6)) * EDIM + (idx & 63)];
            }
        }

        // ---- compute chunk c ----
        #pragma unroll
        for (int ks = 0; ks < 4; ks++) {
            const int k = (ks << 3) + tg;

            uint32_t bh[4][2], bl[4][2];
            #pragma unroll
            for (int nf = 0; nf < 4; nf++) {
                int e = (wc << 5) + (nf << 3) + g;
                split2(sm[B_OFF + k * BSTRIDE + e],       bh[nf][0], bl[nf][0]);
                split2(sm[B_OFF + (k + 4) * BSTRIDE + e], bh[nf][1], bl[nf][1]);
            }

            #pragma unroll
            for (int mf = 0; mf < 2; mf++) {
                int r0 = (wr << 5) + (mf << 4) + g;
                uint32_t ah0, ah1, ah2, ah3, al0, al1, al2, al3;
                split2(sm[A_OFF + r0 * ASTRIDE + k],           ah0, al0);
                split2(sm[A_OFF + (r0 + 8) * ASTRIDE + k],     ah1, al1);
                split2(sm[A_OFF + r0 * ASTRIDE + k + 4],       ah2, al2);
                split2(sm[A_OFF + (r0 + 8) * ASTRIDE + k + 4], ah3, al3);
                #pragma unroll
                for (int nf = 0; nf < 4; nf++) {
                    mma8(acc[mf][nf], ah0, ah1, ah2, ah3, bh[nf][0], bh[nf][1]);
                    mma8(cor[mf][nf], ah0, ah1, ah2, ah3, bl[nf][0], bl[nf][1]);
                    mma8(cor[mf][nf], al0, al1, al2, al3, bh[nf][0], bh[nf][1]);
                }
            }
        }

        // ---- drain hh accumulator into FFMA sums (defeats TC C-add bias) ----
        #pragma unroll
        for (int mf = 0; mf < 2; mf++)
            #pragma unroll
            for (int nf = 0; nf < 4; nf++)
                #pragma unroll
                for (int i = 0; i < 4; i++) {
                    sum[mf][nf][i] += acc[mf][nf][i];
                    acc[mf][nf][i] = 0.0f;
                }

        __syncthreads();   // tiles fully consumed before next store
    }

    // ---- bias/cnt init ----
    if (tid < EDIM) {
        sm[BIAS_OFF + tid] = b[tid];
        ((int*)sm)[CNT_OFF + tid] = 0;
    }

    // ---- spill logits (sum + correction) to smem ----
    {
        float* lg = sm + LG_OFF;
        #pragma unroll
        for (int mf = 0; mf < 2; mf++) {
            int t = (wr << 5) + (mf << 4) + g;
            #pragma unroll
            for (int nf = 0; nf < 4; nf++) {
                int e = (wc << 5) + (nf << 3) + (tg << 1);
                lg[t * LG_STRIDE + e]           = sum[mf][nf][0] + cor[mf][nf][0];
                lg[t * LG_STRIDE + e + 1]       = sum[mf][nf][1] + cor[mf][nf][1];
                lg[(t + 8) * LG_STRIDE + e]     = sum[mf][nf][2] + cor[mf][nf][2];
                lg[(t + 8) * LG_STRIDE + e + 1] = sum[mf][nf][3] + cor[mf][nf][3];
            }
        }
    }
    __syncthreads();

    // ---- per-token: bias + top-2 + softmax + outputs ----
    if (tid < BM) {
        const int m = tid;
        float lg[EDIM];
        #pragma unroll
        for (int e = 0; e < EDIM; e++)
            lg[e] = sm[LG_OFF + m * LG_STRIDE + e] + sm[BIAS_OFF + e];

        float v1 = -3.0e38f, v2 = -3.0e38f;
        int i1 = 0, i2 = 0;
        #pragma unroll
        for (int e = 0; e < EDIM; e++) {
            float l = lg[e];
            if (l > v1)      { v2 = v1; i2 = i1; v1 = l; i1 = e; }
            else if (l > v2) { v2 = l; i2 = e; }
        }
        float s = 0.0f;
        #pragma unroll
        for (int e = 0; e < EDIM; e++) s += __expf(lg[e] - v1);
        float inv = 1.0f / s;

        int gt = row0 + m;
        out[2 * gt + 0] = inv;
        out[2 * gt + 1] = __expf(v2 - v1) * inv;
        float* oi = out + 2 * (size_t)N;
        oi[2 * gt + 0] = (float)i1;
        oi[2 * gt + 1] = (float)i2;

        atomicAdd((int*)sm + CNT_OFF + i1, 1);
        atomicAdd((int*)sm + CNT_OFF + i2, 1);

        #pragma unroll
        for (int e = 0; e < EDIM; e++)
            sm[LG_OFF + m * LG_STRIDE + e] = __expf(lg[e] - v1) * inv;
    }
    __syncthreads();

    // ---- per-expert prob sums + global accumulation ----
    if (tid < EDIM) {
        float s = 0.0f;
        #pragma unroll 8
        for (int m = 0; m < BM; m++)
            s += sm[LG_OFF + m * LG_STRIDE + tid];
        atomicAdd(&g_prob[tid], s);
        atomicAdd(&g_cnt[tid], (float)(((int*)sm)[CNT_OFF + tid]));
    }
}

__global__ void finalize_kernel(float* __restrict__ out, int N) {
    __shared__ float red[64];
    int t = threadIdx.x;
    float invN = 1.0f / (float)N;
    red[t] = (g_cnt[t] * invN) * (g_prob[t] * invN);
    __syncthreads();
    if (t < 32) {
        float s = red[t] + red[t + 32];
        #pragma unroll
        for (int o = 16; o > 0; o >>= 1)
            s += __shfl_down_sync(0xffffffffu, s, o);
        if (t == 0) out[4 * (size_t)N] = (float)EDIM * s;
    }
}

extern "C" void kernel_launch(void* const* d_in, const int* in_sizes, int n_in,
                              void* d_out, int out_size) {
    const float* x = (const float*)d_in[0];
    const float* W = (const float*)d_in[1];
    const float* b = (const float*)d_in[2];
    int N = in_sizes[0] / DDIM;   // 16384

    float* out = (float*)d_out;
    zero_acc_kernel<<<1, 64>>>();
    router_main_kernel<<<N / BM, 256>>>(x, W, b, out, N);
    finalize_kernel<<<1, 64>>>(out, N);
}